// round 12
// baseline (speedup 1.0000x reference)
#include <cuda_runtime.h>
#include <cstdint>

// Problem shapes (fixed by the dataset problem)
#define B 32
#define F 1024
#define S 2048
#define TOPK 16

#define THREADS 256

// colsum micro-units: 32 rows x 1024 cols (half the columns) each.
// 128 units per batch; 512 blocks x 8 sequential groups cover all 32 batches.
#define UNIT_ROWS 32
#define UNITS_PER_BATCH 128            // 64 row-chunks x 2 col-chunks
#define NCOLSUM 512
#define BATCH_GROUP 4                  // batches completed per group
#define NGROUPS (B / BATCH_GROUP)      // 8

#define NTOPK B                        // 32
#define GATHER_PER_B 4
#define NGATHER (B * GATHER_PER_B)     // 128
#define NBLOCKS (NCOLSUM + NTOPK + NGATHER)   // 672 <= 888 wave-1 slots

// Scratch (no allocation allowed in kernel_launch)
__device__ float g_sums[B * S];        // 256 KB, atomically accumulated
__device__ int   g_topk[B * TOPK];
__device__ int   g_cnt[B];             // colsum units done per batch
__device__ int   g_flag[B];            // topk done per batch

// ---------------------------------------------------------------------------
// Reset accumulators + sync state so every graph replay is identical.
// ---------------------------------------------------------------------------
__global__ void reset_kernel() {
    const int i = blockIdx.x * THREADS + threadIdx.x;
    for (int j = i; j < B * S; j += gridDim.x * THREADS) g_sums[j] = 0.f;
    if (i < B) { g_cnt[i] = 0; g_flag[i] = 0; }
}

// ---------------------------------------------------------------------------
// Fused kernel, block-role specialized, with TIME-STAGGERED batch completion:
//   [0, 512)   colsum — each block runs 8 sequential 32-row units, batch-group
//                       ordered: group {0..3} first (all 512 blocks -> done in
//                       ~10us), then {4..7}, ... Batches finish at ~10us
//                       intervals, so topk+gather of early groups overlap the
//                       colsum stream of later groups.
//   [512, 544) topk   — per batch: spin on unit counter, 16x iterative argmax
//                       over g_sums[b] (L2-hot), publish flag.
//   [544, 672) gather — 4 blocks per batch: spin on flag, gather 16 cols/f-row.
// Producers never wait; all 672 blocks wave-1 resident -> no deadlock.
// ---------------------------------------------------------------------------
__global__ void __launch_bounds__(THREADS, 6) fused_kernel(const float* __restrict__ x,
                                                           const float* __restrict__ w,
                                                           float* __restrict__ out) {
    const int bid = blockIdx.x;
    const int t   = threadIdx.x;

    if (bid < NCOLSUM) {
        // ---- colsum role ----
        const int sub  = bid & 127;        // unit within a batch
        const int cc   = sub & 1;          // column half
        const int rc   = sub >> 1;         // row chunk 0..63
        const int bofs = bid >> 7;         // which batch of the group (0..3)
        const int col4 = cc * THREADS + t; // float4 column index (0..511)
        const int str  = S / 4;            // float4 stride per row = 512

        for (int g = 0; g < NGROUPS; g++) {
            const int b = g * BATCH_GROUP + bofs;

            const float4* __restrict__ p =
                reinterpret_cast<const float4*>(
                    w + (size_t)b * S * S + (size_t)(rc * UNIT_ROWS) * S) + col4;

            float4 a0 = make_float4(0.f, 0.f, 0.f, 0.f);
            float4 a1 = a0, a2 = a0, a3 = a0;

            #pragma unroll
            for (int r = 0; r < UNIT_ROWS; r += 4) {
                float4 v0 = __ldcs(p + 0 * str);
                float4 v1 = __ldcs(p + 1 * str);
                float4 v2 = __ldcs(p + 2 * str);
                float4 v3 = __ldcs(p + 3 * str);
                p += 4 * str;
                a0.x += v0.x; a0.y += v0.y; a0.z += v0.z; a0.w += v0.w;
                a1.x += v1.x; a1.y += v1.y; a1.z += v1.z; a1.w += v1.w;
                a2.x += v2.x; a2.y += v2.y; a2.z += v2.z; a2.w += v2.w;
                a3.x += v3.x; a3.y += v3.y; a3.z += v3.z; a3.w += v3.w;
            }

            float* __restrict__ dst = g_sums + (size_t)b * S + col4 * 4;
            atomicAdd(dst + 0, (a0.x + a1.x) + (a2.x + a3.x));
            atomicAdd(dst + 1, (a0.y + a1.y) + (a2.y + a3.y));
            atomicAdd(dst + 2, (a0.z + a1.z) + (a2.z + a3.z));
            atomicAdd(dst + 3, (a0.w + a1.w) + (a2.w + a3.w));

            __syncthreads();               // all threads' REDs issued
            if (t == 0) {
                __threadfence();           // release: REDs visible before count
                atomicAdd(&g_cnt[b], 1);
            }
            // other 255 threads stream straight into next unit's loads
        }

    } else if (bid < NCOLSUM + NTOPK) {
        // ---- topk role (one block per batch) ----
        __shared__ unsigned long long s_warp[THREADS / 32];
        __shared__ unsigned long long s_best;

        const int b    = bid - NCOLSUM;
        const int lane = t & 31;
        const int wid  = t >> 5;

        if (t == 0) {
            while (atomicAdd(&g_cnt[b], 0) < UNITS_PER_BATCH) __nanosleep(256);
        }
        __syncthreads();
        __threadfence();                   // acquire: see g_sums

        float v[8];
        #pragma unroll
        for (int i = 0; i < 8; i++)
            v[i] = g_sums[(size_t)b * S + i * THREADS + t];

        // 16x iterative argmax. Key packing -> descending value, lowest-index
        // tie-break: matches lax.top_k (index order feeds take_along_axis).
        for (int it = 0; it < TOPK; it++) {
            unsigned long long best = 0ull;
            #pragma unroll
            for (int i = 0; i < 8; i++) {
                unsigned fb = __float_as_uint(v[i]);
                fb = (fb & 0x80000000u) ? ~fb : (fb | 0x80000000u);
                unsigned long long key =
                    ((unsigned long long)fb << 32) |
                    (unsigned)(0xFFFFFFFFu - (unsigned)(i * THREADS + t));
                best = (key > best) ? key : best;
            }
            #pragma unroll
            for (int off = 16; off > 0; off >>= 1) {
                unsigned long long o = __shfl_xor_sync(0xFFFFFFFFu, best, off);
                best = (o > best) ? o : best;
            }
            if (lane == 0) s_warp[wid] = best;
            __syncthreads();
            if (t == 0) {
                unsigned long long m = s_warp[0];
                #pragma unroll
                for (int j = 1; j < THREADS / 32; j++)
                    m = (s_warp[j] > m) ? s_warp[j] : m;
                s_best = m;
                g_topk[b * TOPK + it] =
                    (int)(0xFFFFFFFFu - (unsigned)(m & 0xFFFFFFFFull));
            }
            __syncthreads();
            const int c = (int)(0xFFFFFFFFu - (unsigned)(s_best & 0xFFFFFFFFull));
            if ((c & (THREADS - 1)) == t)
                v[c >> 8] = -3.402823466e38f;
        }

        __threadfence();                   // release: g_topk before flag
        __syncthreads();
        if (t == 0) atomicExch(&g_flag[b], 1);

    } else {
        // ---- gather role (4 blocks per batch) ----
        __shared__ int s_idx[TOPK];

        const int g     = bid - (NCOLSUM + NTOPK);
        const int b     = g >> 2;
        const int fpart = g & 3;
        const int f     = fpart * THREADS + t;      // 0..F-1

        if (t == 0) {
            while (atomicAdd(&g_flag[b], 0) == 0) __nanosleep(256);
        }
        __syncthreads();
        __threadfence();                   // acquire: see g_topk
        if (t < TOPK) s_idx[t] = g_topk[b * TOPK + t];
        __syncthreads();

        const float* __restrict__ row = x + ((size_t)b * F + f) * S;

        float r[TOPK];
        #pragma unroll
        for (int k = 0; k < TOPK; k++)
            r[k] = __ldg(row + s_idx[k]);

        float4* __restrict__ o4 =
            reinterpret_cast<float4*>(out + ((size_t)b * F + f) * TOPK);
        #pragma unroll
        for (int j = 0; j < TOPK / 4; j++)
            o4[j] = make_float4(r[4 * j], r[4 * j + 1], r[4 * j + 2], r[4 * j + 3]);
    }
}

// ---------------------------------------------------------------------------
extern "C" void kernel_launch(void* const* d_in, const int* in_sizes, int n_in,
                              void* d_out, int out_size) {
    const float* x = (const float*)d_in[0];   // [B, F, S]
    const float* w = (const float*)d_in[1];   // [B, S, S]
    float* out = (float*)d_out;               // [B, F, TOPK]

    (void)in_sizes; (void)n_in; (void)out_size;

    reset_kernel<<<64, THREADS>>>();
    fused_kernel<<<NBLOCKS, THREADS>>>(x, w, out);
}

// round 13
// speedup vs baseline: 1.1679x; 1.1679x over previous
#include <cuda_runtime.h>
#include <cstdint>

// Problem shapes (fixed by the dataset problem)
#define B 32
#define F 1024
#define S 2048
#define TOPK 16

// colsum tiling (proven config: 82us @ 6.6TB/s = LTS cap; DO NOT TOUCH the loop)
#define ROWCH 8                      // row chunks
#define ROWS_PER_CHUNK (S / ROWCH)   // 256
#define COLCH 2                      // column chunks (256 float4 each)
#define THREADS 256

#define NTOPK B                              // 32 topk blocks
#define GATHER_BLOCKS 512                    // 16 per batch
#define TAIL_BLOCKS (NTOPK + GATHER_BLOCKS)  // 544 (<= 888 wave-1 slots)

// Scratch (no allocation allowed in kernel_launch)
__device__ float g_partials[ROWCH * B * S];   // 2 MB
__device__ int   g_topk[B * TOPK];
__device__ int   g_flag[B];                   // topk done per batch

// ---------------------------------------------------------------------------
// Kernel 1: per-(batch, column) partial sums over row chunks.
// Identical to the config measured at 82us / 83% DRAM (the achieved ceiling).
// Block 0 additionally zeroes the tail-sync flags (tail kernel launches after
// this kernel completes, so ordering is guaranteed; deterministic per replay).
// ---------------------------------------------------------------------------
__global__ void __launch_bounds__(THREADS) colsum_kernel(const float* __restrict__ w) {
    if (blockIdx.x == 0 && blockIdx.y == 0 && threadIdx.x < B)
        g_flag[threadIdx.x] = 0;

    const int b  = blockIdx.y;
    const int cc = blockIdx.x & (COLCH - 1);   // 0..1
    const int rc = blockIdx.x >> 1;            // 0..7

    const int col4 = cc * THREADS + threadIdx.x;       // float4 column index (0..511)
    const int str  = S / 4;                            // float4 stride per row = 512

    const float4* __restrict__ p =
        reinterpret_cast<const float4*>(w + (size_t)b * S * S + (size_t)(rc * ROWS_PER_CHUNK) * S)
        + col4;

    float4 a0 = make_float4(0.f, 0.f, 0.f, 0.f);
    float4 a1 = a0, a2 = a0, a3 = a0;

    #pragma unroll 4
    for (int r = 0; r < ROWS_PER_CHUNK; r += 4) {
        float4 v0 = __ldcs(p + 0 * str);
        float4 v1 = __ldcs(p + 1 * str);
        float4 v2 = __ldcs(p + 2 * str);
        float4 v3 = __ldcs(p + 3 * str);
        p += 4 * str;
        a0.x += v0.x; a0.y += v0.y; a0.z += v0.z; a0.w += v0.w;
        a1.x += v1.x; a1.y += v1.y; a1.z += v1.z; a1.w += v1.w;
        a2.x += v2.x; a2.y += v2.y; a2.z += v2.z; a2.w += v2.w;
        a3.x += v3.x; a3.y += v3.y; a3.z += v3.z; a3.w += v3.w;
    }

    float4 s;
    s.x = (a0.x + a1.x) + (a2.x + a3.x);
    s.y = (a0.y + a1.y) + (a2.y + a3.y);
    s.z = (a0.z + a1.z) + (a2.z + a3.z);
    s.w = (a0.w + a1.w) + (a2.w + a3.w);

    // 2 MB -> lands in L2, re-read immediately by the tail kernel's topk role.
    float4* __restrict__ out4 =
        reinterpret_cast<float4*>(g_partials + ((size_t)rc * B + b) * S);
    out4[col4] = s;
}

// ---------------------------------------------------------------------------
// Kernel 2 (fused tail): topk + gather in one launch.
//   blocks [0, 32)    topk   — fused reduce of the 8 partials (L2-hot),
//                              16x iterative argmax, publish flag[b].
//   blocks [32, 544)  gather — 16 blocks per batch; spin on flag[b]; each
//                              thread loads 4 consecutive-k elements of one
//                              f-row and writes one float4 (warp stores 512B
//                              contiguous).
// topk blocks have the lowest block ids -> wave-1 residency before spinners;
// 544 blocks all fit in one wave regardless -> no deadlock.
// Key packing in topk gives descending-value order with lowest-index
// tie-break — matches lax.top_k (index order feeds take_along_axis).
// ---------------------------------------------------------------------------
__global__ void __launch_bounds__(THREADS, 6) tail_kernel(const float* __restrict__ x,
                                                          float* __restrict__ out) {
    const int bid = blockIdx.x;
    const int t   = threadIdx.x;

    if (bid < NTOPK) {
        // ---- topk role (one block per batch) ----
        __shared__ unsigned long long s_warp[THREADS / 32];
        __shared__ unsigned long long s_best;

        const int b    = bid;
        const int lane = t & 31;
        const int wid  = t >> 5;

        // Fused reduce of the 8 row-chunk partials into registers (L2-hot,
        // written by the just-completed colsum kernel).
        float v[8];
        #pragma unroll
        for (int i = 0; i < 8; i++) {
            const int c = i * THREADS + t;
            float s = 0.f;
            #pragma unroll
            for (int rc = 0; rc < ROWCH; rc++)
                s += g_partials[((size_t)rc * B + b) * S + c];
            v[i] = s;
        }

        for (int it = 0; it < TOPK; it++) {
            unsigned long long best = 0ull;
            #pragma unroll
            for (int i = 0; i < 8; i++) {
                unsigned fb = __float_as_uint(v[i]);
                fb = (fb & 0x80000000u) ? ~fb : (fb | 0x80000000u);  // order-preserving
                unsigned long long key =
                    ((unsigned long long)fb << 32) |
                    (unsigned)(0xFFFFFFFFu - (unsigned)(i * THREADS + t));
                best = (key > best) ? key : best;
            }
            #pragma unroll
            for (int off = 16; off > 0; off >>= 1) {
                unsigned long long o = __shfl_xor_sync(0xFFFFFFFFu, best, off);
                best = (o > best) ? o : best;
            }
            if (lane == 0) s_warp[wid] = best;
            __syncthreads();
            if (t == 0) {
                unsigned long long m = s_warp[0];
                #pragma unroll
                for (int j = 1; j < THREADS / 32; j++)
                    m = (s_warp[j] > m) ? s_warp[j] : m;
                s_best = m;
                g_topk[b * TOPK + it] =
                    (int)(0xFFFFFFFFu - (unsigned)(m & 0xFFFFFFFFull));
            }
            __syncthreads();
            const int c = (int)(0xFFFFFFFFu - (unsigned)(s_best & 0xFFFFFFFFull));
            if ((c & (THREADS - 1)) == t)
                v[c >> 8] = -3.402823466e38f;   // remove winner from pool
        }

        __threadfence();                      // release: g_topk before flag
        __syncthreads();
        if (t == 0) atomicExch(&g_flag[b], 1);

    } else {
        // ---- gather role (16 blocks per batch) ----
        __shared__ int s_idx[TOPK];

        const int g  = bid - NTOPK;           // 0..511
        const int b  = g >> 4;                // batch
        const int fq = g & 15;                // which 64-row slice of f

        if (t == 0) {
            while (atomicAdd(&g_flag[b], 0) == 0) __nanosleep(128);
        }
        __syncthreads();
        __threadfence();                      // acquire: see g_topk
        if (t < TOPK) s_idx[t] = g_topk[b * TOPK + t];
        __syncthreads();

        const int f  = fq * 64 + (t >> 2);    // f-row handled by this thread
        const int kq = t & 3;                 // which 4 consecutive k's

        const float* __restrict__ row = x + ((size_t)b * F + f) * S;

        float r0 = __ldg(row + s_idx[4 * kq + 0]);
        float r1 = __ldg(row + s_idx[4 * kq + 1]);
        float r2 = __ldg(row + s_idx[4 * kq + 2]);
        float r3 = __ldg(row + s_idx[4 * kq + 3]);

        // warp writes 8 f-rows x 64B = 512B contiguous, fully coalesced
        reinterpret_cast<float4*>(out)[((size_t)b * F + f) * (TOPK / 4) + kq] =
            make_float4(r0, r1, r2, r3);
    }
}

// ---------------------------------------------------------------------------
extern "C" void kernel_launch(void* const* d_in, const int* in_sizes, int n_in,
                              void* d_out, int out_size) {
    const float* x = (const float*)d_in[0];   // [B, F, S]
    const float* w = (const float*)d_in[1];   // [B, S, S]
    float* out = (float*)d_out;               // [B, F, TOPK]

    (void)in_sizes; (void)n_in; (void)out_size;

    dim3 grid1(COLCH * ROWCH, B);             // (16, 32) = 512 blocks
    colsum_kernel<<<grid1, THREADS>>>(w);

    tail_kernel<<<TAIL_BLOCKS, THREADS>>>(x, out);
}